// round 14
// baseline (speedup 1.0000x reference)
#include <cuda_runtime.h>
#include <cuda_fp16.h>
#include <cuda_bf16.h>
#include <cstdint>

#define NAc 131072
#define NWc 131072
#define Nc  262144
#define Ec  1048576
#define Hc  128
#define Rc  4
#define HTW 640                      // ht row width: [root | rel0..3]

// ---------------- scratch (static __device__, no runtime alloc) ----------------
__device__ __half g_h0[(size_t)Nc * Hc];            // 64 MB
__device__ __half g_h1[(size_t)Nc * Hc];            // 64 MB
__device__ __half g_ht0[(size_t)Nc * HTW];          // 320 MB (layer 0)
__device__ __half g_ht1[(size_t)Nc * HTW];          // 320 MB (layer 1)
__device__ __half g_wt[180224];                     // fp16 transposed weights
__device__ float  g_inv[(size_t)Nc * Rc];           // 4 MB
__device__ int    g_cnt[(size_t)Nc * Rc];           // 4 MB
__device__ int    g_off[Nc + 1];
__device__ int    g_cur[Nc];
__device__ int    g_elist[Ec];
__device__ int    g_bsum[256];

#define WT_CONV_OFF 16384

__global__ void prep_wt(const float* __restrict__ Wa, const float* __restrict__ Ww,
                        const float* __restrict__ Wroot, const float* __restrict__ Wrel,
                        __half* __restrict__ wt)
{
    int i = blockIdx.x * 256 + threadIdx.x;
    if (i >= 180224) return;
    if (i < 16384) {
        int which = i >> 13;
        int j = i & 8191;
        int n = j >> 6, k = j & 63;
        const float* W = which ? Ww : Wa;
        wt[i] = __float2half(W[k * 128 + n]);
    } else {
        int j = i - 16384;
        int mat = j >> 14;                       // 0..9
        int jj = j & 16383;
        int n = jj >> 7, k = jj & 127;
        int l = mat / 5, cb = mat % 5;
        const float* W = (cb == 0) ? (Wroot + (size_t)l * 16384)
                                   : (Wrel + ((size_t)l * 4 + (cb - 1)) * 16384);
        wt[i] = __float2half(W[k * 128 + n]);
    }
}

// ---------------- CSR build ----------------
__global__ void count_kernel(const int* __restrict__ ei, const int* __restrict__ et,
                             int* __restrict__ cnt) {
    int e = blockIdx.x * blockDim.x + threadIdx.x;
    if (e < Ec) {
        int dst = ei[Ec + e];
        int r = et[e];
        atomicAdd(&cnt[dst * Rc + r], 1);
    }
}

__global__ void __launch_bounds__(256) scan1_kernel(
    const int* __restrict__ cnt, float* __restrict__ inv,
    int* __restrict__ off, int* __restrict__ bsum)
{
    __shared__ int sh[256];
    const int blk = blockIdx.x, tid = threadIdx.x;
    const int base = blk * 1024 + tid * 4;
    int d[4], tot = 0;
#pragma unroll
    for (int j = 0; j < 4; j++) {
        int node = base + j;
        int s = 0;
#pragma unroll
        for (int r = 0; r < 4; r++) {
            int c = cnt[node * 4 + r];
            inv[node * 4 + r] = 1.0f / (float)(c > 0 ? c : 1);
            s += c;
        }
        d[j] = s; tot += s;
    }
    sh[tid] = tot;
    __syncthreads();
    for (int o = 1; o < 256; o <<= 1) {
        int t = (tid >= o) ? sh[tid - o] : 0;
        __syncthreads();
        sh[tid] += t;
        __syncthreads();
    }
    int excl = sh[tid] - tot;
#pragma unroll
    for (int j = 0; j < 4; j++) { off[base + j] = excl; excl += d[j]; }
    if (tid == 255) bsum[blk] = sh[255];
}

__global__ void __launch_bounds__(256) scan3_kernel(
    int* __restrict__ off, const int* __restrict__ bsum, int* __restrict__ cur)
{
    __shared__ int sh[256];
    const int tid = threadIdx.x;
    const int g = blockIdx.x >> 2;
    int v = bsum[tid];
    sh[tid] = (tid < g) ? v : 0;
    __syncthreads();
    for (int o = 128; o; o >>= 1) {
        if (tid < o) sh[tid] += sh[tid + o];
        __syncthreads();
    }
    int basesum = sh[0];
    int i = blockIdx.x * 256 + tid;
    int val = off[i] + basesum;
    off[i] = val;
    cur[i] = val;
    if (i == 0) off[Nc] = Ec;
}

__global__ void fill_kernel(const int* __restrict__ ei, const int* __restrict__ et,
                            int* __restrict__ cur, int* __restrict__ elist) {
    int e = blockIdx.x * blockDim.x + threadIdx.x;
    if (e < Ec) {
        int src = ei[e];
        int dst = ei[Ec + e];
        int r = et[e];
        int pos = atomicAdd(&cur[dst], 1);
        elist[pos] = (src << 2) | r;
    }
}

// ================== fp16 MMA building blocks ==================
#define CLDC    132
#define STG_BUF 20480

__device__ __forceinline__ void mma_f16(float c[4], const uint32_t a[4], const uint32_t b[2]) {
    asm volatile(
        "mma.sync.aligned.m16n8k16.row.col.f32.f16.f16.f32 "
        "{%0,%1,%2,%3}, {%4,%5,%6,%7}, {%8,%9}, {%0,%1,%2,%3};"
        : "+f"(c[0]), "+f"(c[1]), "+f"(c[2]), "+f"(c[3])
        : "r"(a[0]), "r"(a[1]), "r"(a[2]), "r"(a[3]), "r"(b[0]), "r"(b[1]));
}

__device__ __forceinline__ void ldsm4(uint32_t& r0, uint32_t& r1, uint32_t& r2, uint32_t& r3,
                                      uint32_t addr) {
    asm volatile("ldmatrix.sync.aligned.m8n8.x4.shared.b16 {%0,%1,%2,%3}, [%4];"
                 : "=r"(r0), "=r"(r1), "=r"(r2), "=r"(r3) : "r"(addr));
}

extern __shared__ float dyn_smem[];

// ---------------- ht GEMM: one block computes ALL 5 col-blocks of its 128 rows ----
__global__ void __launch_bounds__(256) ht_gemm_f16(
    const __half* __restrict__ A,        // h [N,128] fp16
    const __half* __restrict__ wt,
    int layer,
    const float* __restrict__ bias,      // layer's [128] (cb==0 only)
    __half* __restrict__ ht,
    int rootRowLimit,
    int rowBase)
{
    const size_t row0 = (size_t)blockIdx.x * 128 + rowBase;

    const int tid  = threadIdx.x;
    const int lane = tid & 31;
    const int wid  = tid >> 5;
    const int m0 = (wid >> 1) * 32;
    const int n0 = (wid & 1) * 64;
    const int half_ = lane >> 4;
    const int sub   = lane & 15;

    uint32_t smem_u;
    asm("{.reg .u64 t; cvta.to.shared.u64 t, %1; cvt.u32.u64 %0, t;}"
        : "=r"(smem_u) : "l"(dyn_smem));

    const uint32_t aLane = ((lane & 7) + ((lane >> 3) & 1) * 8) * 80 + ((lane >> 4) & 1) * 16;
    const uint32_t bLane = ((lane & 7) + ((lane >> 4) & 1) * 8) * 80 + ((lane >> 3) & 1) * 16;

    const int s_ar = tid >> 2;
    const int s_ac = (tid & 3) << 3;

    for (int cb = 0; cb < 5; cb++) {
        if (cb == 0 && row0 >= (size_t)rootRowLimit) continue;
        const __half* Bt = wt + WT_CONV_OFF + (size_t)(layer * 5 + cb) * 16384;

        float acc[2][8][4];
#pragma unroll
        for (int mi = 0; mi < 2; mi++)
#pragma unroll
            for (int ni = 0; ni < 8; ni++)
#pragma unroll
                for (int j = 0; j < 4; j++) acc[mi][ni][j] = 0.0f;

        auto stage = [&](int s, int buf) {
            int k0 = s * 32;
            char* base = (char*)dyn_smem + buf * STG_BUF;
#pragma unroll
            for (int i = 0; i < 2; i++) {
                int ar = s_ar + i * 64;
                uint4 av = *(const uint4*)&A[(row0 + ar) * (size_t)Hc + k0 + s_ac];
                *(uint4*)(base + ar * 80 + s_ac * 2) = av;
                uint4 bv = *(const uint4*)&Bt[(size_t)ar * 128 + k0 + s_ac];
                *(uint4*)(base + 10240 + ar * 80 + s_ac * 2) = bv;
            }
        };

        stage(0, 0);
        __syncthreads();

        for (int s = 0; s < 4; s++) {
            int buf = s & 1;
            if (s + 1 < 4) stage(s + 1, buf ^ 1);

            uint32_t Abase = smem_u + buf * STG_BUF;
            uint32_t Bbase = Abase + 10240;
#pragma unroll
            for (int kk = 0; kk < 32; kk += 16) {
                uint32_t a[2][4];
#pragma unroll
                for (int mi = 0; mi < 2; mi++)
                    ldsm4(a[mi][0], a[mi][1], a[mi][2], a[mi][3],
                          Abase + (m0 + mi * 16) * 80 + kk * 2 + aLane);
                uint32_t b[8][2];
#pragma unroll
                for (int nip = 0; nip < 4; nip++)
                    ldsm4(b[2 * nip][0], b[2 * nip][1], b[2 * nip + 1][0], b[2 * nip + 1][1],
                          Bbase + (n0 + nip * 16) * 80 + kk * 2 + bLane);
#pragma unroll
                for (int mi = 0; mi < 2; mi++)
#pragma unroll
                    for (int ni = 0; ni < 8; ni++)
                        mma_f16(acc[mi][ni], a[mi], b[ni]);
            }
            __syncthreads();
        }

        float* Cs = dyn_smem;
        const int t = lane & 3;
        const int g = lane >> 2;
#pragma unroll
        for (int mi = 0; mi < 2; mi++) {
            int r = m0 + mi * 16 + g;
#pragma unroll
            for (int ni = 0; ni < 8; ni++) {
                int cc = n0 + ni * 8 + 2 * t;
                Cs[r * CLDC + cc]           = acc[mi][ni][0];
                Cs[r * CLDC + cc + 1]       = acc[mi][ni][1];
                Cs[(r + 8) * CLDC + cc]     = acc[mi][ni][2];
                Cs[(r + 8) * CLDC + cc + 1] = acc[mi][ni][3];
            }
        }
        __syncthreads();

        float4 bv0 = make_float4(0.f, 0.f, 0.f, 0.f);
        float4 bv1 = bv0;
        if (cb == 0) {
            bv0 = *(const float4*)&bias[sub * 8];
            bv1 = *(const float4*)&bias[sub * 8 + 4];
        }
#pragma unroll
        for (int rr = 0; rr < 8; rr++) {
            int r = wid * 16 + rr * 2 + half_;
            float4 x0 = *(float4*)&Cs[r * CLDC + sub * 8];
            float4 x1 = *(float4*)&Cs[r * CLDC + sub * 8 + 4];
            x0.x += bv0.x; x0.y += bv0.y; x0.z += bv0.z; x0.w += bv0.w;
            x1.x += bv1.x; x1.y += bv1.y; x1.z += bv1.z; x1.w += bv1.w;
            __half2 p0 = __floats2half2_rn(x0.x, x0.y);
            __half2 p1 = __floats2half2_rn(x0.z, x0.w);
            __half2 p2 = __floats2half2_rn(x1.x, x1.y);
            __half2 p3 = __floats2half2_rn(x1.z, x1.w);
            uint4 u = make_uint4(*(uint32_t*)&p0, *(uint32_t*)&p1,
                                 *(uint32_t*)&p2, *(uint32_t*)&p3);
            *(uint4*)&ht[(row0 + r) * HTW + cb * Hc + sub * 8] = u;
        }
        __syncthreads();
    }
}

// ---------------- input projection ----------
__global__ void __launch_bounds__(256) inproj_f16(
    const float* __restrict__ X,
    const __half* __restrict__ Bt,
    const float* __restrict__ bias,
    __half* __restrict__ out)
{
    const size_t row0 = (size_t)blockIdx.x * 128;

    const int tid  = threadIdx.x;
    const int lane = tid & 31;
    const int wid  = tid >> 5;
    const int m0 = (wid >> 1) * 32;
    const int n0 = (wid & 1) * 64;
    const int half_ = lane >> 4;
    const int sub   = lane & 15;

    uint32_t smem_u;
    asm("{.reg .u64 t; cvta.to.shared.u64 t, %1; cvt.u32.u64 %0, t;}"
        : "=r"(smem_u) : "l"(dyn_smem));

    const uint32_t aLane = ((lane & 7) + ((lane >> 3) & 1) * 8) * 80 + ((lane >> 4) & 1) * 16;
    const uint32_t bLane = ((lane & 7) + ((lane >> 4) & 1) * 8) * 80 + ((lane >> 3) & 1) * 16;

    const int s_ar = tid >> 2;
    const int s_ac = (tid & 3) << 3;

    float acc[2][8][4];
#pragma unroll
    for (int mi = 0; mi < 2; mi++)
#pragma unroll
        for (int ni = 0; ni < 8; ni++)
#pragma unroll
            for (int j = 0; j < 4; j++) acc[mi][ni][j] = 0.0f;

    auto stage = [&](int s, int buf) {
        int k0 = s * 32;
        char* base = (char*)dyn_smem + buf * STG_BUF;
#pragma unroll
        for (int i = 0; i < 2; i++) {
            int ar = s_ar + i * 64;
            float4 f0 = *(const float4*)&X[(size_t)(row0 + ar) * 64 + k0 + s_ac];
            float4 f1 = *(const float4*)&X[(size_t)(row0 + ar) * 64 + k0 + s_ac + 4];
            __half2 p0 = __floats2half2_rn(f0.x, f0.y);
            __half2 p1 = __floats2half2_rn(f0.z, f0.w);
            __half2 p2 = __floats2half2_rn(f1.x, f1.y);
            __half2 p3 = __floats2half2_rn(f1.z, f1.w);
            uint4 u = make_uint4(*(uint32_t*)&p0, *(uint32_t*)&p1,
                                 *(uint32_t*)&p2, *(uint32_t*)&p3);
            *(uint4*)(base + ar * 80 + s_ac * 2) = u;
            uint4 bvv = *(const uint4*)&Bt[(size_t)ar * 64 + k0 + s_ac];
            *(uint4*)(base + 10240 + ar * 80 + s_ac * 2) = bvv;
        }
    };

    stage(0, 0);
    __syncthreads();

    for (int s = 0; s < 2; s++) {
        int buf = s & 1;
        if (s + 1 < 2) stage(s + 1, buf ^ 1);

        uint32_t Abase = smem_u + buf * STG_BUF;
        uint32_t Bbase = Abase + 10240;
#pragma unroll
        for (int kk = 0; kk < 32; kk += 16) {
            uint32_t a[2][4];
#pragma unroll
            for (int mi = 0; mi < 2; mi++)
                ldsm4(a[mi][0], a[mi][1], a[mi][2], a[mi][3],
                      Abase + (m0 + mi * 16) * 80 + kk * 2 + aLane);
            uint32_t b[8][2];
#pragma unroll
            for (int nip = 0; nip < 4; nip++)
                ldsm4(b[2 * nip][0], b[2 * nip][1], b[2 * nip + 1][0], b[2 * nip + 1][1],
                      Bbase + (n0 + nip * 16) * 80 + kk * 2 + bLane);
#pragma unroll
            for (int mi = 0; mi < 2; mi++)
#pragma unroll
                for (int ni = 0; ni < 8; ni++)
                    mma_f16(acc[mi][ni], a[mi], b[ni]);
        }
        __syncthreads();
    }

    float* Cs = dyn_smem;
    const int t = lane & 3;
    const int g = lane >> 2;
#pragma unroll
    for (int mi = 0; mi < 2; mi++) {
        int r = m0 + mi * 16 + g;
#pragma unroll
        for (int ni = 0; ni < 8; ni++) {
            int cc = n0 + ni * 8 + 2 * t;
            Cs[r * CLDC + cc]           = acc[mi][ni][0];
            Cs[r * CLDC + cc + 1]       = acc[mi][ni][1];
            Cs[(r + 8) * CLDC + cc]     = acc[mi][ni][2];
            Cs[(r + 8) * CLDC + cc + 1] = acc[mi][ni][3];
        }
    }
    __syncthreads();

    float4 bv0 = *(const float4*)&bias[sub * 8];
    float4 bv1 = *(const float4*)&bias[sub * 8 + 4];
#pragma unroll
    for (int rr = 0; rr < 8; rr++) {
        int r = wid * 16 + rr * 2 + half_;
        float4 x0 = *(float4*)&Cs[r * CLDC + sub * 8];
        float4 x1 = *(float4*)&Cs[r * CLDC + sub * 8 + 4];
        x0.x = fmaxf(x0.x + bv0.x, 0.f); x0.y = fmaxf(x0.y + bv0.y, 0.f);
        x0.z = fmaxf(x0.z + bv0.z, 0.f); x0.w = fmaxf(x0.w + bv0.w, 0.f);
        x1.x = fmaxf(x1.x + bv1.x, 0.f); x1.y = fmaxf(x1.y + bv1.y, 0.f);
        x1.z = fmaxf(x1.z + bv1.z, 0.f); x1.w = fmaxf(x1.w + bv1.w, 0.f);
        __half2 p0 = __floats2half2_rn(x0.x, x0.y);
        __half2 p1 = __floats2half2_rn(x0.z, x0.w);
        __half2 p2 = __floats2half2_rn(x1.x, x1.y);
        __half2 p3 = __floats2half2_rn(x1.z, x1.w);
        uint4 u = make_uint4(*(uint32_t*)&p0, *(uint32_t*)&p1,
                             *(uint32_t*)&p2, *(uint32_t*)&p3);
        *(uint4*)&out[(row0 + r) * Hc + sub * 8] = u;
    }
}

// ---------------- gather + LN + ReLU (+ optional fused output head) ----------------
template<bool HEAD>
__global__ void __launch_bounds__(256) gather_ln_kernel(
    const __half* __restrict__ ht, const int* __restrict__ off,
    const int* __restrict__ elist, const float* __restrict__ inv,
    const float* __restrict__ lng, const float* __restrict__ lnb,
    void* __restrict__ out_v,
    const float* __restrict__ Wout, const float* __restrict__ bout,
    const float* __restrict__ basep,
    int nodeBase)
{
    const int warp = threadIdx.x >> 5;
    const int lane = threadIdx.x & 31;
    const int half = lane >> 4;
    const int sub  = lane & 15;
    const int d = nodeBase + blockIdx.x * 8 + warp;

    float a[8];
#pragma unroll
    for (int j = 0; j < 8; j++) a[j] = 0.0f;

    if (half == 0) {
        uint4 v = *(const uint4*)&ht[(size_t)d * HTW + sub * 8];
        const __half2* h2 = (const __half2*)&v;
#pragma unroll
        for (int j = 0; j < 4; j++) {
            float2 f = __half22float2(h2[j]);
            a[2 * j]     = f.x;
            a[2 * j + 1] = f.y;
        }
    }

    const float4 iv = *(const float4*)&inv[d * 4];
    const int e0 = __ldg(&off[d]);
    const int e1 = __ldg(&off[d + 1]);

    for (int e = e0; e < e1; e += 4) {
#pragma unroll
        for (int q = 0; q < 2; q++) {
            int i = e + half + q * 2;
            if (i < e1) {
                int p = __ldg(&elist[i]);
                int src = p >> 2;
                int r = p & 3;
                float s = (r & 1) ? ((r & 2) ? iv.w : iv.y) : ((r & 2) ? iv.z : iv.x);
                uint4 v = *(const uint4*)&ht[(size_t)src * HTW + (1 + r) * Hc + sub * 8];
                const __half2* h2 = (const __half2*)&v;
#pragma unroll
                for (int j = 0; j < 4; j++) {
                    float2 f = __half22float2(h2[j]);
                    a[2 * j]     += s * f.x;
                    a[2 * j + 1] += s * f.y;
                }
            }
        }
    }

#pragma unroll
    for (int j = 0; j < 8; j++) a[j] += __shfl_xor_sync(0xffffffffu, a[j], 16);

    float sum = 0.f, sq = 0.f;
#pragma unroll
    for (int j = 0; j < 8; j++) { sum += a[j]; sq += a[j] * a[j]; }
#pragma unroll
    for (int o = 8; o; o >>= 1) {
        sum += __shfl_xor_sync(0xffffffffu, sum, o);
        sq  += __shfl_xor_sync(0xffffffffu, sq, o);
    }
    const float inv128 = 1.0f / 128.0f;
    float mu  = sum * inv128;
    float var = sq * inv128 - mu * mu;
    float rs  = rsqrtf(var + 1e-5f);

    float o8[8];
    float4 gv0  = *(const float4*)&lng[sub * 8];
    float4 gv1  = *(const float4*)&lng[sub * 8 + 4];
    float4 lb0  = *(const float4*)&lnb[sub * 8];
    float4 lb1  = *(const float4*)&lnb[sub * 8 + 4];
    const float gg[8] = {gv0.x, gv0.y, gv0.z, gv0.w, gv1.x, gv1.y, gv1.z, gv1.w};
    const float bb[8] = {lb0.x, lb0.y, lb0.z, lb0.w, lb1.x, lb1.y, lb1.z, lb1.w};
#pragma unroll
    for (int j = 0; j < 8; j++)
        o8[j] = fmaxf((a[j] - mu) * rs * gg[j] + bb[j], 0.0f);

    if (HEAD) {
        float4 w0 = *(const float4*)&Wout[sub * 8];
        float4 w1 = *(const float4*)&Wout[sub * 8 + 4];
        const float ww[8] = {w0.x, w0.y, w0.z, w0.w, w1.x, w1.y, w1.z, w1.w};
        float s = 0.f;
#pragma unroll
        for (int j = 0; j < 8; j++) s += o8[j] * ww[j];
#pragma unroll
        for (int o = 8; o; o >>= 1) s += __shfl_xor_sync(0xffffffffu, s, o);
        if (lane == 0) ((float*)out_v)[d] = basep[0] + s + bout[0];
    } else {
        if (half == 0) {
            __half2 p0 = __floats2half2_rn(o8[0], o8[1]);
            __half2 p1 = __floats2half2_rn(o8[2], o8[3]);
            __half2 p2 = __floats2half2_rn(o8[4], o8[5]);
            __half2 p3 = __floats2half2_rn(o8[6], o8[7]);
            uint4 u = make_uint4(*(uint32_t*)&p0, *(uint32_t*)&p1,
                                 *(uint32_t*)&p2, *(uint32_t*)&p3);
            *(uint4*)&((__half*)out_v)[(size_t)d * Hc + sub * 8] = u;
        }
    }
}

// ---------------- launch ----------------
extern "C" void kernel_launch(void* const* d_in, const int* in_sizes, int n_in,
                              void* d_out, int out_size)
{
    const float* xa     = (const float*)d_in[0];
    const float* xw     = (const float*)d_in[1];
    const int*   ei     = (const int*)  d_in[2];
    const int*   et     = (const int*)  d_in[3];
    const float* W_in_a = (const float*)d_in[4];
    const float* b_in_a = (const float*)d_in[5];
    const float* W_in_w = (const float*)d_in[6];
    const float* b_in_w = (const float*)d_in[7];
    const float* W_rel  = (const float*)d_in[8];
    const float* W_root = (const float*)d_in[9];
    const float* b_conv = (const float*)d_in[10];
    const float* ln_g   = (const float*)d_in[11];
    const float* ln_b   = (const float*)d_in[12];
    const float* W_out  = (const float*)d_in[13];
    const float* b_out  = (const float*)d_in[14];
    const float* base   = (const float*)d_in[15];
    float* pred = (float*)d_out;

    void *p_h0, *p_h1, *p_ht0, *p_ht1, *p_wt, *p_inv, *p_cnt, *p_off, *p_cur, *p_elist, *p_bsum;
    cudaGetSymbolAddress(&p_h0, g_h0);
    cudaGetSymbolAddress(&p_h1, g_h1);
    cudaGetSymbolAddress(&p_ht0, g_ht0);
    cudaGetSymbolAddress(&p_ht1, g_ht1);
    cudaGetSymbolAddress(&p_wt, g_wt);
    cudaGetSymbolAddress(&p_inv, g_inv);
    cudaGetSymbolAddress(&p_cnt, g_cnt);
    cudaGetSymbolAddress(&p_off, g_off);
    cudaGetSymbolAddress(&p_cur, g_cur);
    cudaGetSymbolAddress(&p_elist, g_elist);
    cudaGetSymbolAddress(&p_bsum, g_bsum);
    __half* h0  = (__half*)p_h0;
    __half* h1  = (__half*)p_h1;
    __half* ht0 = (__half*)p_ht0;
    __half* ht1 = (__half*)p_ht1;
    __half* wt  = (__half*)p_wt;
    float*  inv = (float*)p_inv;
    int* cnt   = (int*)p_cnt;
    int* off   = (int*)p_off;
    int* cur   = (int*)p_cur;
    int* elist = (int*)p_elist;
    int* bsum  = (int*)p_bsum;

    static cudaStream_t s_csr = nullptr, s_aux = nullptr;
    static cudaEvent_t evF = nullptr, evJ = nullptr, evG1 = nullptr, evH1 = nullptr;
    static bool attr_set = false;
    if (!attr_set) {
        cudaFuncSetAttribute(ht_gemm_f16,
                             cudaFuncAttributeMaxDynamicSharedMemorySize,
                             128 * CLDC * sizeof(float));
        cudaFuncSetAttribute(inproj_f16,
                             cudaFuncAttributeMaxDynamicSharedMemorySize,
                             128 * CLDC * sizeof(float));
        cudaStreamCreateWithFlags(&s_csr, cudaStreamNonBlocking);
        cudaStreamCreateWithFlags(&s_aux, cudaStreamNonBlocking);
        cudaEventCreateWithFlags(&evF, cudaEventDisableTiming);
        cudaEventCreateWithFlags(&evJ, cudaEventDisableTiming);
        cudaEventCreateWithFlags(&evG1, cudaEventDisableTiming);
        cudaEventCreateWithFlags(&evH1, cudaEventDisableTiming);
        attr_set = true;
    }
    const int gemm_smem = 128 * CLDC * sizeof(float);   // 67.6 KB

    // ---- fork: CSR build on side stream ----
    cudaEventRecord(evF, 0);
    cudaStreamWaitEvent(s_csr, evF, 0);
    cudaMemsetAsync(cnt, 0, (size_t)Nc * Rc * sizeof(int), s_csr);
    count_kernel<<<Ec / 256, 256, 0, s_csr>>>(ei, et, cnt);
    scan1_kernel<<<256, 256, 0, s_csr>>>(cnt, inv, off, bsum);
    scan3_kernel<<<Nc / 256, 256, 0, s_csr>>>(off, bsum, cur);
    fill_kernel<<<Ec / 256, 256, 0, s_csr>>>(ei, et, cur, elist);
    cudaEventRecord(evJ, s_csr);

    // ---- main stream: weights, input projections, layer-0 GEMM -> ht0 ----
    prep_wt<<<704, 256>>>(W_in_a, W_in_w, W_root, W_rel, wt);
    inproj_f16<<<NAc / 128, 256, gemm_smem>>>(xa, wt, b_in_a, h0);
    inproj_f16<<<NWc / 128, 256, gemm_smem>>>(xw, wt + 8192, b_in_w, h0 + (size_t)NAc * Hc);
    ht_gemm_f16<<<Nc / 128, 256, gemm_smem>>>(h0, wt, 0, b_conv, ht0, Nc, 0);

    // ---- join CSR, then pipelined gather L0 (reads ht0) / ht_gemm L1 (writes ht1) --
    cudaStreamWaitEvent(0, evJ, 0);
    // gather L0 first half -> h1[0, Nc/2)
    gather_ln_kernel<false><<<(Nc / 2) / 8, 256>>>(ht0, off, elist, inv,
                                                   ln_g, ln_b, h1,
                                                   nullptr, nullptr, nullptr, 0);
    cudaEventRecord(evG1, 0);
    // aux stream: ht_gemm L1 lower half (reads h1 lower half, writes ht1 lower half)
    cudaStreamWaitEvent(s_aux, evG1, 0);
    ht_gemm_f16<<<(Nc / 2) / 128, 256, gemm_smem, s_aux>>>(
        h1, wt, 1, b_conv + Hc, ht1, NAc, 0);
    cudaEventRecord(evH1, s_aux);
    // main: gather L0 second half (reads ht0 — disjoint from ht1 writes)
    gather_ln_kernel<false><<<(Nc / 2) / 8, 256>>>(ht0, off, elist, inv,
                                                   ln_g, ln_b, h1,
                                                   nullptr, nullptr, nullptr, Nc / 2);
    // main: ht_gemm L1 upper half -> ht1
    ht_gemm_f16<<<(Nc / 2) / 128, 256, gemm_smem>>>(
        h1, wt, 1, b_conv + Hc, ht1, NAc, Nc / 2);

    // ---- join aux, final gather + head (reads ht1) ----
    cudaStreamWaitEvent(0, evH1, 0);
    gather_ln_kernel<true><<<NAc / 8, 256>>>(ht1, off, elist, inv,
                                             ln_g + Hc, ln_b + Hc, pred,
                                             W_out, b_out, base, 0);
}

// round 16
// speedup vs baseline: 1.1254x; 1.1254x over previous
#include <cuda_runtime.h>
#include <cuda_fp16.h>
#include <cuda_bf16.h>
#include <cstdint>

#define NAc 131072
#define NWc 131072
#define Nc  262144
#define Ec  1048576
#define Hc  128
#define Rc  4
#define HTW 640                      // ht row width: [root | rel0..3]

// ---------------- scratch (static __device__, no runtime alloc) ----------------
__device__ __half g_h0[(size_t)Nc * Hc];            // 64 MB
__device__ __half g_h1[(size_t)Nc * Hc];            // 64 MB
__device__ __half g_ht[(size_t)Nc * HTW];           // 320 MB
__device__ __half g_wt[180224];                     // fp16 transposed weights
__device__ float  g_inv[(size_t)Nc * Rc];           // 4 MB
__device__ int    g_cnt[(size_t)Nc * Rc];           // 4 MB
__device__ int    g_off[Nc + 1];
__device__ int    g_cur[Nc];
__device__ int    g_elist[Ec];
__device__ int    g_bsum[256];

// g_wt layout (halves):
//   [0      : 8192)   W_in_a^T  [n=128][k=64]
//   [8192   : 16384)  W_in_w^T  [n=128][k=64]
//   [16384 + (l*5+cb)*16384 ...)  layer l, col-block cb: W^T [n=128][k=128]
#define WT_CONV_OFF 16384

__global__ void prep_wt(const float* __restrict__ Wa, const float* __restrict__ Ww,
                        const float* __restrict__ Wroot, const float* __restrict__ Wrel,
                        __half* __restrict__ wt)
{
    int i = blockIdx.x * 256 + threadIdx.x;
    if (i >= 180224) return;
    if (i < 16384) {
        int which = i >> 13;
        int j = i & 8191;
        int n = j >> 6, k = j & 63;
        const float* W = which ? Ww : Wa;
        wt[i] = __float2half(W[k * 128 + n]);
    } else {
        int j = i - 16384;
        int mat = j >> 14;                       // 0..9
        int jj = j & 16383;
        int n = jj >> 7, k = jj & 127;
        int l = mat / 5, cb = mat % 5;
        const float* W = (cb == 0) ? (Wroot + (size_t)l * 16384)
                                   : (Wrel + ((size_t)l * 4 + (cb - 1)) * 16384);
        wt[i] = __float2half(W[k * 128 + n]);
    }
}

// ---------------- CSR build ----------------
__global__ void count_kernel(const int* __restrict__ ei, const int* __restrict__ et,
                             int* __restrict__ cnt) {
    int e = blockIdx.x * blockDim.x + threadIdx.x;
    if (e < Ec) {
        int dst = ei[Ec + e];
        int r = et[e];
        atomicAdd(&cnt[dst * Rc + r], 1);
    }
}

__global__ void __launch_bounds__(256) scan1_kernel(
    const int* __restrict__ cnt, float* __restrict__ inv,
    int* __restrict__ off, int* __restrict__ bsum)
{
    __shared__ int sh[256];
    const int blk = blockIdx.x, tid = threadIdx.x;
    const int base = blk * 1024 + tid * 4;
    int d[4], tot = 0;
#pragma unroll
    for (int j = 0; j < 4; j++) {
        int node = base + j;
        int s = 0;
#pragma unroll
        for (int r = 0; r < 4; r++) {
            int c = cnt[node * 4 + r];
            inv[node * 4 + r] = 1.0f / (float)(c > 0 ? c : 1);
            s += c;
        }
        d[j] = s; tot += s;
    }
    sh[tid] = tot;
    __syncthreads();
    for (int o = 1; o < 256; o <<= 1) {
        int t = (tid >= o) ? sh[tid - o] : 0;
        __syncthreads();
        sh[tid] += t;
        __syncthreads();
    }
    int excl = sh[tid] - tot;
#pragma unroll
    for (int j = 0; j < 4; j++) { off[base + j] = excl; excl += d[j]; }
    if (tid == 255) bsum[blk] = sh[255];
}

// scan3 with scan2 folded in
__global__ void __launch_bounds__(256) scan3_kernel(
    int* __restrict__ off, const int* __restrict__ bsum, int* __restrict__ cur)
{
    __shared__ int sh[256];
    const int tid = threadIdx.x;
    const int g = blockIdx.x >> 2;
    int v = bsum[tid];
    sh[tid] = (tid < g) ? v : 0;
    __syncthreads();
    for (int o = 128; o; o >>= 1) {
        if (tid < o) sh[tid] += sh[tid + o];
        __syncthreads();
    }
    int basesum = sh[0];
    int i = blockIdx.x * 256 + tid;
    int val = off[i] + basesum;
    off[i] = val;
    cur[i] = val;
    if (i == 0) off[Nc] = Ec;
}

__global__ void fill_kernel(const int* __restrict__ ei, const int* __restrict__ et,
                            int* __restrict__ cur, int* __restrict__ elist) {
    int e = blockIdx.x * blockDim.x + threadIdx.x;
    if (e < Ec) {
        int src = ei[e];
        int dst = ei[Ec + e];
        int r = et[e];
        int pos = atomicAdd(&cur[dst], 1);
        elist[pos] = (src << 2) | r;
    }
}

// ================== fp16 MMA building blocks ==================
#define CLDC    132
#define STG_BUF 20480               // bytes per stage buffer (A 10240 + B 10240)

__device__ __forceinline__ void mma_f16(float c[4], const uint32_t a[4], const uint32_t b[2]) {
    asm volatile(
        "mma.sync.aligned.m16n8k16.row.col.f32.f16.f16.f32 "
        "{%0,%1,%2,%3}, {%4,%5,%6,%7}, {%8,%9}, {%0,%1,%2,%3};"
        : "+f"(c[0]), "+f"(c[1]), "+f"(c[2]), "+f"(c[3])
        : "r"(a[0]), "r"(a[1]), "r"(a[2]), "r"(a[3]), "r"(b[0]), "r"(b[1]));
}

__device__ __forceinline__ void ldsm4(uint32_t& r0, uint32_t& r1, uint32_t& r2, uint32_t& r3,
                                      uint32_t addr) {
    asm volatile("ldmatrix.sync.aligned.m8n8.x4.shared.b16 {%0,%1,%2,%3}, [%4];"
                 : "=r"(r0), "=r"(r1), "=r"(r2), "=r"(r3) : "r"(addr));
}

extern __shared__ float dyn_smem[];

// ---------------- ht GEMM: one block computes ALL 5 col-blocks of its 128 rows ----
__global__ void __launch_bounds__(256) ht_gemm_f16(
    const __half* __restrict__ A,        // h [N,128] fp16
    const __half* __restrict__ wt,       // g_wt
    int layer,
    const float* __restrict__ bias,      // layer's [128] (cb==0 only)
    __half* __restrict__ ht,
    int rootRowLimit)
{
    const size_t row0 = (size_t)blockIdx.x * 128;

    const int tid  = threadIdx.x;
    const int lane = tid & 31;
    const int wid  = tid >> 5;
    const int m0 = (wid >> 1) * 32;
    const int n0 = (wid & 1) * 64;
    const int half_ = lane >> 4;
    const int sub   = lane & 15;

    uint32_t smem_u;
    asm("{.reg .u64 t; cvta.to.shared.u64 t, %1; cvt.u32.u64 %0, t;}"
        : "=r"(smem_u) : "l"(dyn_smem));

    const uint32_t aLane = ((lane & 7) + ((lane >> 3) & 1) * 8) * 80 + ((lane >> 4) & 1) * 16;
    const uint32_t bLane = ((lane & 7) + ((lane >> 4) & 1) * 8) * 80 + ((lane >> 3) & 1) * 16;

    const int s_ar = tid >> 2;            // 0..63
    const int s_ac = (tid & 3) << 3;      // 0,8,16,24 (halves)

    for (int cb = 0; cb < 5; cb++) {
        if (cb == 0 && row0 >= (size_t)rootRowLimit) continue;
        const __half* Bt = wt + WT_CONV_OFF + (size_t)(layer * 5 + cb) * 16384;

        float acc[2][8][4];
#pragma unroll
        for (int mi = 0; mi < 2; mi++)
#pragma unroll
            for (int ni = 0; ni < 8; ni++)
#pragma unroll
                for (int j = 0; j < 4; j++) acc[mi][ni][j] = 0.0f;

        auto stage = [&](int s, int buf) {
            int k0 = s * 32;
            char* base = (char*)dyn_smem + buf * STG_BUF;
#pragma unroll
            for (int i = 0; i < 2; i++) {
                int ar = s_ar + i * 64;
                uint4 av = *(const uint4*)&A[(row0 + ar) * (size_t)Hc + k0 + s_ac];
                *(uint4*)(base + ar * 80 + s_ac * 2) = av;
                uint4 bv = *(const uint4*)&Bt[(size_t)ar * 128 + k0 + s_ac];
                *(uint4*)(base + 10240 + ar * 80 + s_ac * 2) = bv;
            }
        };

        stage(0, 0);
        __syncthreads();

        for (int s = 0; s < 4; s++) {
            int buf = s & 1;
            if (s + 1 < 4) stage(s + 1, buf ^ 1);

            uint32_t Abase = smem_u + buf * STG_BUF;
            uint32_t Bbase = Abase + 10240;
#pragma unroll
            for (int kk = 0; kk < 32; kk += 16) {
                uint32_t a[2][4];
#pragma unroll
                for (int mi = 0; mi < 2; mi++)
                    ldsm4(a[mi][0], a[mi][1], a[mi][2], a[mi][3],
                          Abase + (m0 + mi * 16) * 80 + kk * 2 + aLane);
                uint32_t b[8][2];
#pragma unroll
                for (int nip = 0; nip < 4; nip++)
                    ldsm4(b[2 * nip][0], b[2 * nip][1], b[2 * nip + 1][0], b[2 * nip + 1][1],
                          Bbase + (n0 + nip * 16) * 80 + kk * 2 + bLane);
#pragma unroll
                for (int mi = 0; mi < 2; mi++)
#pragma unroll
                    for (int ni = 0; ni < 8; ni++)
                        mma_f16(acc[mi][ni], a[mi], b[ni]);
            }
            __syncthreads();
        }

        // epilogue for this cb: fp32 dump to smem, then fp16 stores
        float* Cs = dyn_smem;
        const int t = lane & 3;
        const int g = lane >> 2;
#pragma unroll
        for (int mi = 0; mi < 2; mi++) {
            int r = m0 + mi * 16 + g;
#pragma unroll
            for (int ni = 0; ni < 8; ni++) {
                int cc = n0 + ni * 8 + 2 * t;
                Cs[r * CLDC + cc]           = acc[mi][ni][0];
                Cs[r * CLDC + cc + 1]       = acc[mi][ni][1];
                Cs[(r + 8) * CLDC + cc]     = acc[mi][ni][2];
                Cs[(r + 8) * CLDC + cc + 1] = acc[mi][ni][3];
            }
        }
        __syncthreads();

        float4 bv0 = make_float4(0.f, 0.f, 0.f, 0.f);
        float4 bv1 = bv0;
        if (cb == 0) {
            bv0 = *(const float4*)&bias[sub * 8];
            bv1 = *(const float4*)&bias[sub * 8 + 4];
        }
#pragma unroll
        for (int rr = 0; rr < 8; rr++) {
            int r = wid * 16 + rr * 2 + half_;
            float4 x0 = *(float4*)&Cs[r * CLDC + sub * 8];
            float4 x1 = *(float4*)&Cs[r * CLDC + sub * 8 + 4];
            x0.x += bv0.x; x0.y += bv0.y; x0.z += bv0.z; x0.w += bv0.w;
            x1.x += bv1.x; x1.y += bv1.y; x1.z += bv1.z; x1.w += bv1.w;
            __half2 p0 = __floats2half2_rn(x0.x, x0.y);
            __half2 p1 = __floats2half2_rn(x0.z, x0.w);
            __half2 p2 = __floats2half2_rn(x1.x, x1.y);
            __half2 p3 = __floats2half2_rn(x1.z, x1.w);
            uint4 u = make_uint4(*(uint32_t*)&p0, *(uint32_t*)&p1,
                                 *(uint32_t*)&p2, *(uint32_t*)&p3);
            *(uint4*)&ht[(row0 + r) * HTW + cb * Hc + sub * 8] = u;
        }
        __syncthreads();   // Cs region is reused as staging for the next cb
    }
}

// ---------------- input projection (both halves in one grid) ----------
__global__ void __launch_bounds__(256) inproj_f16(
    const float* __restrict__ Xa, const float* __restrict__ Xw,
    const __half* __restrict__ wt,
    const float* __restrict__ bia, const float* __restrict__ biw,
    __half* __restrict__ out)
{
    const size_t row0 = (size_t)blockIdx.x * 128;
    const float* X     = (row0 < NAc) ? Xa + row0 * 64 : Xw + (row0 - NAc) * 64;
    const float* bias  = (row0 < NAc) ? bia : biw;
    const __half* Bt   = (row0 < NAc) ? wt : wt + 8192;

    const int tid  = threadIdx.x;
    const int lane = tid & 31;
    const int wid  = tid >> 5;
    const int m0 = (wid >> 1) * 32;
    const int n0 = (wid & 1) * 64;
    const int half_ = lane >> 4;
    const int sub   = lane & 15;

    uint32_t smem_u;
    asm("{.reg .u64 t; cvta.to.shared.u64 t, %1; cvt.u32.u64 %0, t;}"
        : "=r"(smem_u) : "l"(dyn_smem));

    const uint32_t aLane = ((lane & 7) + ((lane >> 3) & 1) * 8) * 80 + ((lane >> 4) & 1) * 16;
    const uint32_t bLane = ((lane & 7) + ((lane >> 4) & 1) * 8) * 80 + ((lane >> 3) & 1) * 16;

    const int s_ar = tid >> 2;
    const int s_ac = (tid & 3) << 3;

    float acc[2][8][4];
#pragma unroll
    for (int mi = 0; mi < 2; mi++)
#pragma unroll
        for (int ni = 0; ni < 8; ni++)
#pragma unroll
            for (int j = 0; j < 4; j++) acc[mi][ni][j] = 0.0f;

    auto stage = [&](int s, int buf) {
        int k0 = s * 32;
        char* base = (char*)dyn_smem + buf * STG_BUF;
#pragma unroll
        for (int i = 0; i < 2; i++) {
            int ar = s_ar + i * 64;
            float4 f0 = *(const float4*)&X[(size_t)ar * 64 + k0 + s_ac];
            float4 f1 = *(const float4*)&X[(size_t)ar * 64 + k0 + s_ac + 4];
            __half2 p0 = __floats2half2_rn(f0.x, f0.y);
            __half2 p1 = __floats2half2_rn(f0.z, f0.w);
            __half2 p2 = __floats2half2_rn(f1.x, f1.y);
            __half2 p3 = __floats2half2_rn(f1.z, f1.w);
            uint4 u = make_uint4(*(uint32_t*)&p0, *(uint32_t*)&p1,
                                 *(uint32_t*)&p2, *(uint32_t*)&p3);
            *(uint4*)(base + ar * 80 + s_ac * 2) = u;
            uint4 bvv = *(const uint4*)&Bt[(size_t)ar * 64 + k0 + s_ac];
            *(uint4*)(base + 10240 + ar * 80 + s_ac * 2) = bvv;
        }
    };

    stage(0, 0);
    __syncthreads();

    for (int s = 0; s < 2; s++) {
        int buf = s & 1;
        if (s + 1 < 2) stage(s + 1, buf ^ 1);

        uint32_t Abase = smem_u + buf * STG_BUF;
        uint32_t Bbase = Abase + 10240;
#pragma unroll
        for (int kk = 0; kk < 32; kk += 16) {
            uint32_t a[2][4];
#pragma unroll
            for (int mi = 0; mi < 2; mi++)
                ldsm4(a[mi][0], a[mi][1], a[mi][2], a[mi][3],
                      Abase + (m0 + mi * 16) * 80 + kk * 2 + aLane);
            uint32_t b[8][2];
#pragma unroll
            for (int nip = 0; nip < 4; nip++)
                ldsm4(b[2 * nip][0], b[2 * nip][1], b[2 * nip + 1][0], b[2 * nip + 1][1],
                      Bbase + (n0 + nip * 16) * 80 + kk * 2 + bLane);
#pragma unroll
            for (int mi = 0; mi < 2; mi++)
#pragma unroll
                for (int ni = 0; ni < 8; ni++)
                    mma_f16(acc[mi][ni], a[mi], b[ni]);
        }
        __syncthreads();
    }

    float* Cs = dyn_smem;
    const int t = lane & 3;
    const int g = lane >> 2;
#pragma unroll
    for (int mi = 0; mi < 2; mi++) {
        int r = m0 + mi * 16 + g;
#pragma unroll
        for (int ni = 0; ni < 8; ni++) {
            int cc = n0 + ni * 8 + 2 * t;
            Cs[r * CLDC + cc]           = acc[mi][ni][0];
            Cs[r * CLDC + cc + 1]       = acc[mi][ni][1];
            Cs[(r + 8) * CLDC + cc]     = acc[mi][ni][2];
            Cs[(r + 8) * CLDC + cc + 1] = acc[mi][ni][3];
        }
    }
    __syncthreads();

    float4 bv0 = *(const float4*)&bias[sub * 8];
    float4 bv1 = *(const float4*)&bias[sub * 8 + 4];
#pragma unroll
    for (int rr = 0; rr < 8; rr++) {
        int r = wid * 16 + rr * 2 + half_;
        float4 x0 = *(float4*)&Cs[r * CLDC + sub * 8];
        float4 x1 = *(float4*)&Cs[r * CLDC + sub * 8 + 4];
        x0.x = fmaxf(x0.x + bv0.x, 0.f); x0.y = fmaxf(x0.y + bv0.y, 0.f);
        x0.z = fmaxf(x0.z + bv0.z, 0.f); x0.w = fmaxf(x0.w + bv0.w, 0.f);
        x1.x = fmaxf(x1.x + bv1.x, 0.f); x1.y = fmaxf(x1.y + bv1.y, 0.f);
        x1.z = fmaxf(x1.z + bv1.z, 0.f); x1.w = fmaxf(x1.w + bv1.w, 0.f);
        __half2 p0 = __floats2half2_rn(x0.x, x0.y);
        __half2 p1 = __floats2half2_rn(x0.z, x0.w);
        __half2 p2 = __floats2half2_rn(x1.x, x1.y);
        __half2 p3 = __floats2half2_rn(x1.z, x1.w);
        uint4 u = make_uint4(*(uint32_t*)&p0, *(uint32_t*)&p1,
                             *(uint32_t*)&p2, *(uint32_t*)&p3);
        *(uint4*)&out[(row0 + r) * Hc + sub * 8] = u;
    }
}

// ---------------- gather + LN + ReLU (+ optional fused output head) ----------------
template<bool HEAD>
__global__ void __launch_bounds__(256) gather_ln_kernel(
    const __half* __restrict__ ht, const int* __restrict__ off,
    const int* __restrict__ elist, const float* __restrict__ inv,
    const float* __restrict__ lng, const float* __restrict__ lnb,
    void* __restrict__ out_v,
    const float* __restrict__ Wout, const float* __restrict__ bout,
    const float* __restrict__ basep)
{
    const int warp = threadIdx.x >> 5;
    const int lane = threadIdx.x & 31;
    const int half = lane >> 4;
    const int sub  = lane & 15;
    const int d = blockIdx.x * 8 + warp;

    float a[8];
#pragma unroll
    for (int j = 0; j < 8; j++) a[j] = 0.0f;

    if (half == 0) {
        uint4 v = *(const uint4*)&ht[(size_t)d * HTW + sub * 8];
        const __half2* h2 = (const __half2*)&v;
#pragma unroll
        for (int j = 0; j < 4; j++) {
            float2 f = __half22float2(h2[j]);
            a[2 * j]     = f.x;
            a[2 * j + 1] = f.y;
        }
    }

    const float4 iv = *(const float4*)&inv[d * 4];
    const int e0 = __ldg(&off[d]);
    const int e1 = __ldg(&off[d + 1]);

    for (int e = e0; e < e1; e += 4) {
#pragma unroll
        for (int q = 0; q < 2; q++) {
            int i = e + half + q * 2;
            if (i < e1) {
                int p = __ldg(&elist[i]);
                int src = p >> 2;
                int r = p & 3;
                float s = (r & 1) ? ((r & 2) ? iv.w : iv.y) : ((r & 2) ? iv.z : iv.x);
                uint4 v = *(const uint4*)&ht[(size_t)src * HTW + (1 + r) * Hc + sub * 8];
                const __half2* h2 = (const __half2*)&v;
#pragma unroll
                for (int j = 0; j < 4; j++) {
                    float2 f = __half22float2(h2[j]);
                    a[2 * j]     += s * f.x;
                    a[2 * j + 1] += s * f.y;
                }
            }
        }
    }

#pragma unroll
    for (int j = 0; j < 8; j++) a[j] += __shfl_xor_sync(0xffffffffu, a[j], 16);

    float sum = 0.f, sq = 0.f;
#pragma unroll
    for (int j = 0; j < 8; j++) { sum += a[j]; sq += a[j] * a[j]; }
#pragma unroll
    for (int o = 8; o; o >>= 1) {
        sum += __shfl_xor_sync(0xffffffffu, sum, o);
        sq  += __shfl_xor_sync(0xffffffffu, sq, o);
    }
    const float inv128 = 1.0f / 128.0f;
    float mu  = sum * inv128;
    float var = sq * inv128 - mu * mu;
    float rs  = rsqrtf(var + 1e-5f);

    float o8[8];
    float4 gv0  = *(const float4*)&lng[sub * 8];
    float4 gv1  = *(const float4*)&lng[sub * 8 + 4];
    float4 lb0  = *(const float4*)&lnb[sub * 8];
    float4 lb1  = *(const float4*)&lnb[sub * 8 + 4];
    const float gg[8] = {gv0.x, gv0.y, gv0.z, gv0.w, gv1.x, gv1.y, gv1.z, gv1.w};
    const float bb[8] = {lb0.x, lb0.y, lb0.z, lb0.w, lb1.x, lb1.y, lb1.z, lb1.w};
#pragma unroll
    for (int j = 0; j < 8; j++)
        o8[j] = fmaxf((a[j] - mu) * rs * gg[j] + bb[j], 0.0f);

    if (HEAD) {
        float4 w0 = *(const float4*)&Wout[sub * 8];
        float4 w1 = *(const float4*)&Wout[sub * 8 + 4];
        const float ww[8] = {w0.x, w0.y, w0.z, w0.w, w1.x, w1.y, w1.z, w1.w};
        float s = 0.f;
#pragma unroll
        for (int j = 0; j < 8; j++) s += o8[j] * ww[j];
#pragma unroll
        for (int o = 8; o; o >>= 1) s += __shfl_xor_sync(0xffffffffu, s, o);
        if (lane == 0) ((float*)out_v)[d] = basep[0] + s + bout[0];
    } else {
        if (half == 0) {
            __half2 p0 = __floats2half2_rn(o8[0], o8[1]);
            __half2 p1 = __floats2half2_rn(o8[2], o8[3]);
            __half2 p2 = __floats2half2_rn(o8[4], o8[5]);
            __half2 p3 = __floats2half2_rn(o8[6], o8[7]);
            uint4 u = make_uint4(*(uint32_t*)&p0, *(uint32_t*)&p1,
                                 *(uint32_t*)&p2, *(uint32_t*)&p3);
            *(uint4*)&((__half*)out_v)[(size_t)d * Hc + sub * 8] = u;
        }
    }
}

// ---------------- launch ----------------
extern "C" void kernel_launch(void* const* d_in, const int* in_sizes, int n_in,
                              void* d_out, int out_size)
{
    const float* xa     = (const float*)d_in[0];
    const float* xw     = (const float*)d_in[1];
    const int*   ei     = (const int*)  d_in[2];
    const int*   et     = (const int*)  d_in[3];
    const float* W_in_a = (const float*)d_in[4];
    const float* b_in_a = (const float*)d_in[5];
    const float* W_in_w = (const float*)d_in[6];
    const float* b_in_w = (const float*)d_in[7];
    const float* W_rel  = (const float*)d_in[8];
    const float* W_root = (const float*)d_in[9];
    const float* b_conv = (const float*)d_in[10];
    const float* ln_g   = (const float*)d_in[11];
    const float* ln_b   = (const float*)d_in[12];
    const float* W_out  = (const float*)d_in[13];
    const float* b_out  = (const float*)d_in[14];
    const float* base   = (const float*)d_in[15];
    float* pred = (float*)d_out;

    void *p_h0, *p_h1, *p_ht, *p_wt, *p_inv, *p_cnt, *p_off, *p_cur, *p_elist, *p_bsum;
    cudaGetSymbolAddress(&p_h0, g_h0);
    cudaGetSymbolAddress(&p_h1, g_h1);
    cudaGetSymbolAddress(&p_ht, g_ht);
    cudaGetSymbolAddress(&p_wt, g_wt);
    cudaGetSymbolAddress(&p_inv, g_inv);
    cudaGetSymbolAddress(&p_cnt, g_cnt);
    cudaGetSymbolAddress(&p_off, g_off);
    cudaGetSymbolAddress(&p_cur, g_cur);
    cudaGetSymbolAddress(&p_elist, g_elist);
    cudaGetSymbolAddress(&p_bsum, g_bsum);
    __half* h0  = (__half*)p_h0;
    __half* h1  = (__half*)p_h1;
    __half* ht  = (__half*)p_ht;
    __half* wt  = (__half*)p_wt;
    float*  inv = (float*)p_inv;
    int* cnt   = (int*)p_cnt;
    int* off   = (int*)p_off;
    int* cur   = (int*)p_cur;
    int* elist = (int*)p_elist;
    int* bsum  = (int*)p_bsum;

    static cudaStream_t s_csr = nullptr;
    static cudaEvent_t evF = nullptr, evJ = nullptr;
    static bool attr_set = false;
    if (!attr_set) {
        cudaFuncSetAttribute(ht_gemm_f16,
                             cudaFuncAttributeMaxDynamicSharedMemorySize,
                             128 * CLDC * sizeof(float));
        cudaFuncSetAttribute(inproj_f16,
                             cudaFuncAttributeMaxDynamicSharedMemorySize,
                             128 * CLDC * sizeof(float));
        cudaStreamCreateWithFlags(&s_csr, cudaStreamNonBlocking);
        cudaEventCreateWithFlags(&evF, cudaEventDisableTiming);
        cudaEventCreateWithFlags(&evJ, cudaEventDisableTiming);
        attr_set = true;
    }
    const int gemm_smem = 128 * CLDC * sizeof(float);   // 67.6 KB

    // ---- fork: CSR build on side stream (independent of dense path) ----
    cudaEventRecord(evF, 0);
    cudaStreamWaitEvent(s_csr, evF, 0);
    cudaMemsetAsync(cnt, 0, (size_t)Nc * Rc * sizeof(int), s_csr);
    count_kernel<<<Ec / 256, 256, 0, s_csr>>>(ei, et, cnt);
    scan1_kernel<<<256, 256, 0, s_csr>>>(cnt, inv, off, bsum);
    scan3_kernel<<<Nc / 256, 256, 0, s_csr>>>(off, bsum, cur);
    fill_kernel<<<Ec / 256, 256, 0, s_csr>>>(ei, et, cur, elist);
    cudaEventRecord(evJ, s_csr);

    // ---- main stream: weights, input projection (single grid), layer-0 GEMM ----
    prep_wt<<<704, 256>>>(W_in_a, W_in_w, W_root, W_rel, wt);
    inproj_f16<<<Nc / 128, 256, gemm_smem>>>(xa, xw, wt, b_in_a, b_in_w, h0);
    ht_gemm_f16<<<Nc / 128, 256, gemm_smem>>>(h0, wt, 0, b_conv, ht, Nc);

    // ---- join, then layer-0 gather ----
    cudaStreamWaitEvent(0, evJ, 0);
    gather_ln_kernel<false><<<Nc / 8, 256>>>(ht, off, elist, inv,
                                             ln_g, ln_b, h1,
                                             nullptr, nullptr, nullptr);

    // ---- layer 1 (root cols only for assignment nodes; fused output head) ----
    ht_gemm_f16<<<Nc / 128, 256, gemm_smem>>>(h1, wt, 1, b_conv + Hc, ht, NAc);
    gather_ln_kernel<true><<<NAc / 8, 256>>>(ht, off, elist, inv,
                                             ln_g + Hc, ln_b + Hc, pred,
                                             W_out, b_out, base);
}

// round 17
// speedup vs baseline: 1.2530x; 1.1134x over previous
#include <cuda_runtime.h>
#include <cuda_fp16.h>
#include <cuda_bf16.h>
#include <cstdint>

#define NAc 131072
#define NWc 131072
#define Nc  262144
#define Ec  1048576
#define Hc  128
#define Rc  4
#define HTW 640                      // ht row width: [root | rel0..3]

// ---------------- scratch (static __device__, no runtime alloc) ----------------
__device__ __half g_h0[(size_t)Nc * Hc];            // 64 MB
__device__ __half g_h1[(size_t)Nc * Hc];            // 64 MB
__device__ __half g_ht[(size_t)Nc * HTW];           // 320 MB
__device__ __half g_wt[180224];                     // fp16 transposed weights
__device__ float  g_inv[(size_t)Nc * Rc];           // 4 MB
__device__ int    g_cnt[(size_t)Nc * Rc];           // 4 MB
__device__ int    g_off[Nc + 1];
__device__ int    g_cur[Nc];
__device__ int    g_elist[Ec];
__device__ int    g_bsum[256];

// g_wt layout (halves):
//   [0      : 8192)   W_in_a^T  [n=128][k=64]
//   [8192   : 16384)  W_in_w^T  [n=128][k=64]
//   [16384 + (l*5+cb)*16384 ...)  layer l, col-block cb: W^T [n=128][k=128]
#define WT_CONV_OFF 16384

__global__ void prep_wt(const float* __restrict__ Wa, const float* __restrict__ Ww,
                        const float* __restrict__ Wroot, const float* __restrict__ Wrel,
                        __half* __restrict__ wt)
{
    int i = blockIdx.x * 256 + threadIdx.x;
    if (i >= 180224) return;
    if (i < 16384) {
        int which = i >> 13;
        int j = i & 8191;
        int n = j >> 6, k = j & 63;
        const float* W = which ? Ww : Wa;
        wt[i] = __float2half(W[k * 128 + n]);
    } else {
        int j = i - 16384;
        int mat = j >> 14;                       // 0..9
        int jj = j & 16383;
        int n = jj >> 7, k = jj & 127;
        int l = mat / 5, cb = mat % 5;
        const float* W = (cb == 0) ? (Wroot + (size_t)l * 16384)
                                   : (Wrel + ((size_t)l * 4 + (cb - 1)) * 16384);
        wt[i] = __float2half(W[k * 128 + n]);
    }
}

// ---------------- CSR build ----------------
__global__ void count_kernel(const int* __restrict__ ei, const int* __restrict__ et,
                             int* __restrict__ cnt) {
    int e = blockIdx.x * blockDim.x + threadIdx.x;
    if (e < Ec) {
        int dst = ei[Ec + e];
        int r = et[e];
        atomicAdd(&cnt[dst * Rc + r], 1);
    }
}

__global__ void __launch_bounds__(256) scan1_kernel(
    const int* __restrict__ cnt, float* __restrict__ inv,
    int* __restrict__ off, int* __restrict__ bsum)
{
    __shared__ int sh[256];
    const int blk = blockIdx.x, tid = threadIdx.x;
    const int base = blk * 1024 + tid * 4;
    int d[4], tot = 0;
#pragma unroll
    for (int j = 0; j < 4; j++) {
        int node = base + j;
        int s = 0;
#pragma unroll
        for (int r = 0; r < 4; r++) {
            int c = cnt[node * 4 + r];
            inv[node * 4 + r] = 1.0f / (float)(c > 0 ? c : 1);
            s += c;
        }
        d[j] = s; tot += s;
    }
    sh[tid] = tot;
    __syncthreads();
    for (int o = 1; o < 256; o <<= 1) {
        int t = (tid >= o) ? sh[tid - o] : 0;
        __syncthreads();
        sh[tid] += t;
        __syncthreads();
    }
    int excl = sh[tid] - tot;
#pragma unroll
    for (int j = 0; j < 4; j++) { off[base + j] = excl; excl += d[j]; }
    if (tid == 255) bsum[blk] = sh[255];
}

// scan3 with scan2 folded in
__global__ void __launch_bounds__(256) scan3_kernel(
    int* __restrict__ off, const int* __restrict__ bsum, int* __restrict__ cur)
{
    __shared__ int sh[256];
    const int tid = threadIdx.x;
    const int g = blockIdx.x >> 2;
    int v = bsum[tid];
    sh[tid] = (tid < g) ? v : 0;
    __syncthreads();
    for (int o = 128; o; o >>= 1) {
        if (tid < o) sh[tid] += sh[tid + o];
        __syncthreads();
    }
    int basesum = sh[0];
    int i = blockIdx.x * 256 + tid;
    int val = off[i] + basesum;
    off[i] = val;
    cur[i] = val;
    if (i == 0) off[Nc] = Ec;
}

__global__ void fill_kernel(const int* __restrict__ ei, const int* __restrict__ et,
                            int* __restrict__ cur, int* __restrict__ elist) {
    int e = blockIdx.x * blockDim.x + threadIdx.x;
    if (e < Ec) {
        int src = ei[e];
        int dst = ei[Ec + e];
        int r = et[e];
        int pos = atomicAdd(&cur[dst], 1);
        elist[pos] = (src << 2) | r;
    }
}

// ================== fp16 MMA building blocks ==================
#define CLDC    132
#define CLDH2   68                  // half2 row stride for fast epilogue
#define STG_BUF 20480               // bytes per stage buffer (A 10240 + B 10240)

__device__ __forceinline__ void mma_f16(float c[4], const uint32_t a[4], const uint32_t b[2]) {
    asm volatile(
        "mma.sync.aligned.m16n8k16.row.col.f32.f16.f16.f32 "
        "{%0,%1,%2,%3}, {%4,%5,%6,%7}, {%8,%9}, {%0,%1,%2,%3};"
        : "+f"(c[0]), "+f"(c[1]), "+f"(c[2]), "+f"(c[3])
        : "r"(a[0]), "r"(a[1]), "r"(a[2]), "r"(a[3]), "r"(b[0]), "r"(b[1]));
}

__device__ __forceinline__ void ldsm4(uint32_t& r0, uint32_t& r1, uint32_t& r2, uint32_t& r3,
                                      uint32_t addr) {
    asm volatile("ldmatrix.sync.aligned.m8n8.x4.shared.b16 {%0,%1,%2,%3}, [%4];"
                 : "=r"(r0), "=r"(r1), "=r"(r2), "=r"(r3) : "r"(addr));
}

extern __shared__ float dyn_smem[];

// ---------------- ht GEMM: one block computes ALL 5 col-blocks of its 128 rows ----
__global__ void __launch_bounds__(256) ht_gemm_f16(
    const __half* __restrict__ A,        // h [N,128] fp16
    const __half* __restrict__ wt,       // g_wt
    int layer,
    const float* __restrict__ bias,      // layer's [128] (cb==0 only)
    __half* __restrict__ ht,
    int rootRowLimit)
{
    const size_t row0 = (size_t)blockIdx.x * 128;

    const int tid  = threadIdx.x;
    const int lane = tid & 31;
    const int wid  = tid >> 5;
    const int m0 = (wid >> 1) * 32;
    const int n0 = (wid & 1) * 64;
    const int half_ = lane >> 4;
    const int sub   = lane & 15;

    uint32_t smem_u;
    asm("{.reg .u64 t; cvta.to.shared.u64 t, %1; cvt.u32.u64 %0, t;}"
        : "=r"(smem_u) : "l"(dyn_smem));

    const uint32_t aLane = ((lane & 7) + ((lane >> 3) & 1) * 8) * 80 + ((lane >> 4) & 1) * 16;
    const uint32_t bLane = ((lane & 7) + ((lane >> 4) & 1) * 8) * 80 + ((lane >> 3) & 1) * 16;

    const int s_ar = tid >> 2;            // 0..63
    const int s_ac = (tid & 3) << 3;      // 0,8,16,24 (halves)

    for (int cb = 0; cb < 5; cb++) {
        if (cb == 0 && row0 >= (size_t)rootRowLimit) continue;
        const __half* Bt = wt + WT_CONV_OFF + (size_t)(layer * 5 + cb) * 16384;

        float acc[2][8][4];
#pragma unroll
        for (int mi = 0; mi < 2; mi++)
#pragma unroll
            for (int ni = 0; ni < 8; ni++)
#pragma unroll
                for (int j = 0; j < 4; j++) acc[mi][ni][j] = 0.0f;

        auto stage = [&](int s, int buf) {
            int k0 = s * 32;
            char* base = (char*)dyn_smem + buf * STG_BUF;
#pragma unroll
            for (int i = 0; i < 2; i++) {
                int ar = s_ar + i * 64;
                uint4 av = *(const uint4*)&A[(row0 + ar) * (size_t)Hc + k0 + s_ac];
                *(uint4*)(base + ar * 80 + s_ac * 2) = av;
                uint4 bv = *(const uint4*)&Bt[(size_t)ar * 128 + k0 + s_ac];
                *(uint4*)(base + 10240 + ar * 80 + s_ac * 2) = bv;
            }
        };

        stage(0, 0);
        __syncthreads();

        for (int s = 0; s < 4; s++) {
            int buf = s & 1;
            if (s + 1 < 4) stage(s + 1, buf ^ 1);

            uint32_t Abase = smem_u + buf * STG_BUF;
            uint32_t Bbase = Abase + 10240;
#pragma unroll
            for (int kk = 0; kk < 32; kk += 16) {
                uint32_t a[2][4];
#pragma unroll
                for (int mi = 0; mi < 2; mi++)
                    ldsm4(a[mi][0], a[mi][1], a[mi][2], a[mi][3],
                          Abase + (m0 + mi * 16) * 80 + kk * 2 + aLane);
                uint32_t b[8][2];
#pragma unroll
                for (int nip = 0; nip < 4; nip++)
                    ldsm4(b[2 * nip][0], b[2 * nip][1], b[2 * nip + 1][0], b[2 * nip + 1][1],
                          Bbase + (n0 + nip * 16) * 80 + kk * 2 + bLane);
#pragma unroll
                for (int mi = 0; mi < 2; mi++)
#pragma unroll
                    for (int ni = 0; ni < 8; ni++)
                        mma_f16(acc[mi][ni], a[mi], b[ni]);
            }
            __syncthreads();
        }

        const int t = lane & 3;
        const int g = lane >> 2;

        if (cb == 0) {
            // ---- slow path with bias (fp32 smem round trip; bit-identical to R16) ----
            float* Cs = dyn_smem;
#pragma unroll
            for (int mi = 0; mi < 2; mi++) {
                int r = m0 + mi * 16 + g;
#pragma unroll
                for (int ni = 0; ni < 8; ni++) {
                    int cc = n0 + ni * 8 + 2 * t;
                    Cs[r * CLDC + cc]           = acc[mi][ni][0];
                    Cs[r * CLDC + cc + 1]       = acc[mi][ni][1];
                    Cs[(r + 8) * CLDC + cc]     = acc[mi][ni][2];
                    Cs[(r + 8) * CLDC + cc + 1] = acc[mi][ni][3];
                }
            }
            __syncthreads();

            float4 bv0 = *(const float4*)&bias[sub * 8];
            float4 bv1 = *(const float4*)&bias[sub * 8 + 4];
#pragma unroll
            for (int rr = 0; rr < 8; rr++) {
                int r = wid * 16 + rr * 2 + half_;
                float4 x0 = *(float4*)&Cs[r * CLDC + sub * 8];
                float4 x1 = *(float4*)&Cs[r * CLDC + sub * 8 + 4];
                x0.x += bv0.x; x0.y += bv0.y; x0.z += bv0.z; x0.w += bv0.w;
                x1.x += bv1.x; x1.y += bv1.y; x1.z += bv1.z; x1.w += bv1.w;
                __half2 p0 = __floats2half2_rn(x0.x, x0.y);
                __half2 p1 = __floats2half2_rn(x0.z, x0.w);
                __half2 p2 = __floats2half2_rn(x1.x, x1.y);
                __half2 p3 = __floats2half2_rn(x1.z, x1.w);
                uint4 u = make_uint4(*(uint32_t*)&p0, *(uint32_t*)&p1,
                                     *(uint32_t*)&p2, *(uint32_t*)&p3);
                *(uint4*)&ht[(row0 + r) * HTW + cb * Hc + sub * 8] = u;
            }
        } else {
            // ---- fast path, no bias: convert in-register, half2 smem transpose ----
            __half2* Csh = (__half2*)dyn_smem;   // row stride CLDH2 half2 (128*68*4 = 34.8 KB)
#pragma unroll
            for (int mi = 0; mi < 2; mi++) {
                int r = m0 + mi * 16 + g;
                int cc2 = (n0 >> 1) + t;
#pragma unroll
                for (int ni = 0; ni < 8; ni++) {
                    Csh[r * CLDH2 + cc2 + ni * 4]       = __floats2half2_rn(acc[mi][ni][0], acc[mi][ni][1]);
                    Csh[(r + 8) * CLDH2 + cc2 + ni * 4] = __floats2half2_rn(acc[mi][ni][2], acc[mi][ni][3]);
                }
            }
            __syncthreads();
#pragma unroll
            for (int rr = 0; rr < 8; rr++) {
                int r = wid * 16 + rr * 2 + half_;
                uint4 u = *(uint4*)&Csh[r * CLDH2 + sub * 4];
                *(uint4*)&ht[(row0 + r) * HTW + cb * Hc + sub * 8] = u;
            }
        }
        __syncthreads();   // smem reused as staging for the next cb
    }
}

// ---------------- input projection (both halves in one grid) ----------
__global__ void __launch_bounds__(256) inproj_f16(
    const float* __restrict__ Xa, const float* __restrict__ Xw,
    const __half* __restrict__ wt,
    const float* __restrict__ bia, const float* __restrict__ biw,
    __half* __restrict__ out)
{
    const size_t row0 = (size_t)blockIdx.x * 128;
    const float* X     = (row0 < NAc) ? Xa + row0 * 64 : Xw + (row0 - NAc) * 64;
    const float* bias  = (row0 < NAc) ? bia : biw;
    const __half* Bt   = (row0 < NAc) ? wt : wt + 8192;

    const int tid  = threadIdx.x;
    const int lane = tid & 31;
    const int wid  = tid >> 5;
    const int m0 = (wid >> 1) * 32;
    const int n0 = (wid & 1) * 64;
    const int half_ = lane >> 4;
    const int sub   = lane & 15;

    uint32_t smem_u;
    asm("{.reg .u64 t; cvta.to.shared.u64 t, %1; cvt.u32.u64 %0, t;}"
        : "=r"(smem_u) : "l"(dyn_smem));

    const uint32_t aLane = ((lane & 7) + ((lane >> 3) & 1) * 8) * 80 + ((lane >> 4) & 1) * 16;
    const uint32_t bLane = ((lane & 7) + ((lane >> 4) & 1) * 8) * 80 + ((lane >> 3) & 1) * 16;

    const int s_ar = tid >> 2;
    const int s_ac = (tid & 3) << 3;

    float acc[2][8][4];
#pragma unroll
    for (int mi = 0; mi < 2; mi++)
#pragma unroll
        for (int ni = 0; ni < 8; ni++)
#pragma unroll
            for (int j = 0; j < 4; j++) acc[mi][ni][j] = 0.0f;

    auto stage = [&](int s, int buf) {
        int k0 = s * 32;
        char* base = (char*)dyn_smem + buf * STG_BUF;
#pragma unroll
        for (int i = 0; i < 2; i++) {
            int ar = s_ar + i * 64;
            float4 f0 = *(const float4*)&X[(size_t)ar * 64 + k0 + s_ac];
            float4 f1 = *(const float4*)&X[(size_t)ar * 64 + k0 + s_ac + 4];
            __half2 p0 = __floats2half2_rn(f0.x, f0.y);
            __half2 p1 = __floats2half2_rn(f0.z, f0.w);
            __half2 p2 = __floats2half2_rn(f1.x, f1.y);
            __half2 p3 = __floats2half2_rn(f1.z, f1.w);
            uint4 u = make_uint4(*(uint32_t*)&p0, *(uint32_t*)&p1,
                                 *(uint32_t*)&p2, *(uint32_t*)&p3);
            *(uint4*)(base + ar * 80 + s_ac * 2) = u;
            uint4 bvv = *(const uint4*)&Bt[(size_t)ar * 64 + k0 + s_ac];
            *(uint4*)(base + 10240 + ar * 80 + s_ac * 2) = bvv;
        }
    };

    stage(0, 0);
    __syncthreads();

    for (int s = 0; s < 2; s++) {
        int buf = s & 1;
        if (s + 1 < 2) stage(s + 1, buf ^ 1);

        uint32_t Abase = smem_u + buf * STG_BUF;
        uint32_t Bbase = Abase + 10240;
#pragma unroll
        for (int kk = 0; kk < 32; kk += 16) {
            uint32_t a[2][4];
#pragma unroll
            for (int mi = 0; mi < 2; mi++)
                ldsm4(a[mi][0], a[mi][1], a[mi][2], a[mi][3],
                      Abase + (m0 + mi * 16) * 80 + kk * 2 + aLane);
            uint32_t b[8][2];
#pragma unroll
            for (int nip = 0; nip < 4; nip++)
                ldsm4(b[2 * nip][0], b[2 * nip][1], b[2 * nip + 1][0], b[2 * nip + 1][1],
                      Bbase + (n0 + nip * 16) * 80 + kk * 2 + bLane);
#pragma unroll
            for (int mi = 0; mi < 2; mi++)
#pragma unroll
                for (int ni = 0; ni < 8; ni++)
                    mma_f16(acc[mi][ni], a[mi], b[ni]);
        }
        __syncthreads();
    }

    float* Cs = dyn_smem;
    const int t = lane & 3;
    const int g = lane >> 2;
#pragma unroll
    for (int mi = 0; mi < 2; mi++) {
        int r = m0 + mi * 16 + g;
#pragma unroll
        for (int ni = 0; ni < 8; ni++) {
            int cc = n0 + ni * 8 + 2 * t;
            Cs[r * CLDC + cc]           = acc[mi][ni][0];
            Cs[r * CLDC + cc + 1]       = acc[mi][ni][1];
            Cs[(r + 8) * CLDC + cc]     = acc[mi][ni][2];
            Cs[(r + 8) * CLDC + cc + 1] = acc[mi][ni][3];
        }
    }
    __syncthreads();

    float4 bv0 = *(const float4*)&bias[sub * 8];
    float4 bv1 = *(const float4*)&bias[sub * 8 + 4];
#pragma unroll
    for (int rr = 0; rr < 8; rr++) {
        int r = wid * 16 + rr * 2 + half_;
        float4 x0 = *(float4*)&Cs[r * CLDC + sub * 8];
        float4 x1 = *(float4*)&Cs[r * CLDC + sub * 8 + 4];
        x0.x = fmaxf(x0.x + bv0.x, 0.f); x0.y = fmaxf(x0.y + bv0.y, 0.f);
        x0.z = fmaxf(x0.z + bv0.z, 0.f); x0.w = fmaxf(x0.w + bv0.w, 0.f);
        x1.x = fmaxf(x1.x + bv1.x, 0.f); x1.y = fmaxf(x1.y + bv1.y, 0.f);
        x1.z = fmaxf(x1.z + bv1.z, 0.f); x1.w = fmaxf(x1.w + bv1.w, 0.f);
        __half2 p0 = __floats2half2_rn(x0.x, x0.y);
        __half2 p1 = __floats2half2_rn(x0.z, x0.w);
        __half2 p2 = __floats2half2_rn(x1.x, x1.y);
        __half2 p3 = __floats2half2_rn(x1.z, x1.w);
        uint4 u = make_uint4(*(uint32_t*)&p0, *(uint32_t*)&p1,
                             *(uint32_t*)&p2, *(uint32_t*)&p3);
        *(uint4*)&out[(row0 + r) * Hc + sub * 8] = u;
    }
}

// ---------------- gather + LN + ReLU (+ optional fused output head) ----------------
template<bool HEAD>
__global__ void __launch_bounds__(256) gather_ln_kernel(
    const __half* __restrict__ ht, const int* __restrict__ off,
    const int* __restrict__ elist, const float* __restrict__ inv,
    const float* __restrict__ lng, const float* __restrict__ lnb,
    void* __restrict__ out_v,
    const float* __restrict__ Wout, const float* __restrict__ bout,
    const float* __restrict__ basep)
{
    const int warp = threadIdx.x >> 5;
    const int lane = threadIdx.x & 31;
    const int half = lane >> 4;
    const int sub  = lane & 15;
    const int d = blockIdx.x * 8 + warp;

    float a[8];
#pragma unroll
    for (int j = 0; j < 8; j++) a[j] = 0.0f;

    if (half == 0) {
        uint4 v = *(const uint4*)&ht[(size_t)d * HTW + sub * 8];
        const __half2* h2 = (const __half2*)&v;
#pragma unroll
        for (int j = 0; j < 4; j++) {
            float2 f = __half22float2(h2[j]);
            a[2 * j]     = f.x;
            a[2 * j + 1] = f.y;
        }
    }

    const float4 iv = *(const float4*)&inv[d * 4];
    const int e0 = __ldg(&off[d]);
    const int e1 = __ldg(&off[d + 1]);

    for (int e = e0; e < e1; e += 4) {
#pragma unroll
        for (int q = 0; q < 2; q++) {
            int i = e + half + q * 2;
            if (i < e1) {
                int p = __ldg(&elist[i]);
                int src = p >> 2;
                int r = p & 3;
                float s = (r & 1) ? ((r & 2) ? iv.w : iv.y) : ((r & 2) ? iv.z : iv.x);
                uint4 v = *(const uint4*)&ht[(size_t)src * HTW + (1 + r) * Hc + sub * 8];
                const __half2* h2 = (const __half2*)&v;
#pragma unroll
                for (int j = 0; j < 4; j++) {
                    float2 f = __half22float2(h2[j]);
                    a[2 * j]     += s * f.x;
                    a[2 * j + 1] += s * f.y;
                }
            }
        }
    }

#pragma unroll
    for (int j = 0; j < 8; j++) a[j] += __shfl_xor_sync(0xffffffffu, a[j], 16);

    float sum = 0.f, sq = 0.f;
#pragma unroll
    for (int j = 0; j < 8; j++) { sum += a[j]; sq += a[j] * a[j]; }
#pragma unroll
    for (int o = 8; o; o >>= 1) {
        sum += __shfl_xor_sync(0xffffffffu, sum, o);
        sq  += __shfl_xor_sync(0xffffffffu, sq, o);
    }
    const float inv128 = 1.0f / 128.0f;
    float mu  = sum * inv128;
    float var = sq * inv128 - mu * mu;
    float rs  = rsqrtf(var + 1e-5f);

    float o8[8];
    float4 gv0  = *(const float4*)&lng[sub * 8];
    float4 gv1  = *(const float4*)&lng[sub * 8 + 4];
    float4 lb0  = *(const float4*)&lnb[sub * 8];
    float4 lb1  = *(const float4*)&lnb[sub * 8 + 4];
    const float gg[8] = {gv0.x, gv0.y, gv0.z, gv0.w, gv1.x, gv1.y, gv1.z, gv1.w};
    const float bb[8] = {lb0.x, lb0.y, lb0.z, lb0.w, lb1.x, lb1.y, lb1.z, lb1.w};
#pragma unroll
    for (int j = 0; j < 8; j++)
        o8[j] = fmaxf((a[j] - mu) * rs * gg[j] + bb[j], 0.0f);

    if (HEAD) {
        float4 w0 = *(const float4*)&Wout[sub * 8];
        float4 w1 = *(const float4*)&Wout[sub * 8 + 4];
        const float ww[8] = {w0.x, w0.y, w0.z, w0.w, w1.x, w1.y, w1.z, w1.w};
        float s = 0.f;
#pragma unroll
        for (int j = 0; j < 8; j++) s += o8[j] * ww[j];
#pragma unroll
        for (int o = 8; o; o >>= 1) s += __shfl_xor_sync(0xffffffffu, s, o);
        if (lane == 0) ((float*)out_v)[d] = basep[0] + s + bout[0];
    } else {
        if (half == 0) {
            __half2 p0 = __floats2half2_rn(o8[0], o8[1]);
            __half2 p1 = __floats2half2_rn(o8[2], o8[3]);
            __half2 p2 = __floats2half2_rn(o8[4], o8[5]);
            __half2 p3 = __floats2half2_rn(o8[6], o8[7]);
            uint4 u = make_uint4(*(uint32_t*)&p0, *(uint32_t*)&p1,
                                 *(uint32_t*)&p2, *(uint32_t*)&p3);
            *(uint4*)&((__half*)out_v)[(size_t)d * Hc + sub * 8] = u;
        }
    }
}

// ---------------- launch ----------------
extern "C" void kernel_launch(void* const* d_in, const int* in_sizes, int n_in,
                              void* d_out, int out_size)
{
    const float* xa     = (const float*)d_in[0];
    const float* xw     = (const float*)d_in[1];
    const int*   ei     = (const int*)  d_in[2];
    const int*   et     = (const int*)  d_in[3];
    const float* W_in_a = (const float*)d_in[4];
    const float* b_in_a = (const float*)d_in[5];
    const float* W_in_w = (const float*)d_in[6];
    const float* b_in_w = (const float*)d_in[7];
    const float* W_rel  = (const float*)d_in[8];
    const float* W_root = (const float*)d_in[9];
    const float* b_conv = (const float*)d_in[10];
    const float* ln_g   = (const float*)d_in[11];
    const float* ln_b   = (const float*)d_in[12];
    const float* W_out  = (const float*)d_in[13];
    const float* b_out  = (const float*)d_in[14];
    const float* base   = (const float*)d_in[15];
    float* pred = (float*)d_out;

    void *p_h0, *p_h1, *p_ht, *p_wt, *p_inv, *p_cnt, *p_off, *p_cur, *p_elist, *p_bsum;
    cudaGetSymbolAddress(&p_h0, g_h0);
    cudaGetSymbolAddress(&p_h1, g_h1);
    cudaGetSymbolAddress(&p_ht, g_ht);
    cudaGetSymbolAddress(&p_wt, g_wt);
    cudaGetSymbolAddress(&p_inv, g_inv);
    cudaGetSymbolAddress(&p_cnt, g_cnt);
    cudaGetSymbolAddress(&p_off, g_off);
    cudaGetSymbolAddress(&p_cur, g_cur);
    cudaGetSymbolAddress(&p_elist, g_elist);
    cudaGetSymbolAddress(&p_bsum, g_bsum);
    __half* h0  = (__half*)p_h0;
    __half* h1  = (__half*)p_h1;
    __half* ht  = (__half*)p_ht;
    __half* wt  = (__half*)p_wt;
    float*  inv = (float*)p_inv;
    int* cnt   = (int*)p_cnt;
    int* off   = (int*)p_off;
    int* cur   = (int*)p_cur;
    int* elist = (int*)p_elist;
    int* bsum  = (int*)p_bsum;

    static cudaStream_t s_csr = nullptr;
    static cudaEvent_t evF = nullptr, evJ = nullptr;
    static bool attr_set = false;
    if (!attr_set) {
        cudaFuncSetAttribute(ht_gemm_f16,
                             cudaFuncAttributeMaxDynamicSharedMemorySize,
                             128 * CLDC * sizeof(float));
        cudaFuncSetAttribute(inproj_f16,
                             cudaFuncAttributeMaxDynamicSharedMemorySize,
                             128 * CLDC * sizeof(float));
        cudaStreamCreateWithFlags(&s_csr, cudaStreamNonBlocking);
        cudaEventCreateWithFlags(&evF, cudaEventDisableTiming);
        cudaEventCreateWithFlags(&evJ, cudaEventDisableTiming);
        attr_set = true;
    }
    const int gemm_smem = 128 * CLDC * sizeof(float);   // 67.6 KB

    // ---- fork: CSR build on side stream (independent of dense path) ----
    cudaEventRecord(evF, 0);
    cudaStreamWaitEvent(s_csr, evF, 0);
    cudaMemsetAsync(cnt, 0, (size_t)Nc * Rc * sizeof(int), s_csr);
    count_kernel<<<Ec / 256, 256, 0, s_csr>>>(ei, et, cnt);
    scan1_kernel<<<256, 256, 0, s_csr>>>(cnt, inv, off, bsum);
    scan3_kernel<<<Nc / 256, 256, 0, s_csr>>>(off, bsum, cur);
    fill_kernel<<<Ec / 256, 256, 0, s_csr>>>(ei, et, cur, elist);
    cudaEventRecord(evJ, s_csr);

    // ---- main stream: weights, input projection (single grid), layer-0 GEMM ----
    prep_wt<<<704, 256>>>(W_in_a, W_in_w, W_root, W_rel, wt);
    inproj_f16<<<Nc / 128, 256, gemm_smem>>>(xa, xw, wt, b_in_a, b_in_w, h0);
    ht_gemm_f16<<<Nc / 128, 256, gemm_smem>>>(h0, wt, 0, b_conv, ht, Nc);

    // ---- join, then layer-0 gather ----
    cudaStreamWaitEvent(0, evJ, 0);
    gather_ln_kernel<false><<<Nc / 8, 256>>>(ht, off, elist, inv,
                                             ln_g, ln_b, h1,
                                             nullptr, nullptr, nullptr);

    // ---- layer 1 (root cols only for assignment nodes; fused output head) ----
    ht_gemm_f16<<<Nc / 128, 256, gemm_smem>>>(h1, wt, 1, b_conv + Hc, ht, NAc);
    gather_ln_kernel<true><<<NAc / 8, 256>>>(ht, off, elist, inv,
                                             ln_g + Hc, ln_b + Hc, pred,
                                             W_out, b_out, base);
}